// round 5
// baseline (speedup 1.0000x reference)
#include <cuda_runtime.h>
#include <math.h>

#define BB 64
#define SS 4096
#define DD 256
#define SPLIT 32
#define ROWS_PER_SPLIT (SS / SPLIT)   // 128

// Scratch (no allocation allowed in kernel_launch)
__device__ float g_score[BB * SS];
__device__ float g_weight[BB * SS];
__device__ float g_partial[SPLIT * BB * DD];

// ---------------------------------------------------------------------------
// Kernel 1: per-row LayerNorm-folded score.
// One warp per (b,s) row. Each lane owns 8 consecutive d's (2x float4).
// score = rs*(sum(x*g*w) - mu*sum(g*w)) + sum(beta*w) + bias, masked.
// ---------------------------------------------------------------------------
__global__ __launch_bounds__(256) void score_kernel(
    const float* __restrict__ x, const float* __restrict__ mask,
    const float* __restrict__ gamma, const float* __restrict__ beta,
    const float* __restrict__ w, const float* __restrict__ bias)
{
    const int warp = (blockIdx.x * blockDim.x + threadIdx.x) >> 5;
    const int lane = threadIdx.x & 31;
    if (warp >= BB * SS) return;

    const float* row = x + (size_t)warp * DD;
    const int d0 = lane * 8;

    const float4 a  = *(const float4*)(row + d0);
    const float4 c  = *(const float4*)(row + d0 + 4);
    const float4 g1 = *(const float4*)(gamma + d0);
    const float4 g2 = *(const float4*)(gamma + d0 + 4);
    const float4 w1 = *(const float4*)(w + d0);
    const float4 w2 = *(const float4*)(w + d0 + 4);
    const float4 b1 = *(const float4*)(beta + d0);
    const float4 b2 = *(const float4*)(beta + d0 + 4);

    // gamma*w per element
    const float gw0 = g1.x * w1.x, gw1 = g1.y * w1.y, gw2 = g1.z * w1.z, gw3 = g1.w * w1.w;
    const float gw4 = g2.x * w2.x, gw5 = g2.y * w2.y, gw6 = g2.z * w2.z, gw7 = g2.w * w2.w;

    float sx   = a.x + a.y + a.z + a.w + c.x + c.y + c.z + c.w;
    float sx2  = a.x*a.x + a.y*a.y + a.z*a.z + a.w*a.w
               + c.x*c.x + c.y*c.y + c.z*c.z + c.w*c.w;
    float sxgw = a.x*gw0 + a.y*gw1 + a.z*gw2 + a.w*gw3
               + c.x*gw4 + c.y*gw5 + c.z*gw6 + c.w*gw7;
    float sgw  = gw0 + gw1 + gw2 + gw3 + gw4 + gw5 + gw6 + gw7;
    float sbw  = b1.x*w1.x + b1.y*w1.y + b1.z*w1.z + b1.w*w1.w
               + b2.x*w2.x + b2.y*w2.y + b2.z*w2.z + b2.w*w2.w;

    #pragma unroll
    for (int o = 16; o > 0; o >>= 1) {
        sx   += __shfl_xor_sync(0xffffffffu, sx,   o);
        sx2  += __shfl_xor_sync(0xffffffffu, sx2,  o);
        sxgw += __shfl_xor_sync(0xffffffffu, sxgw, o);
        sgw  += __shfl_xor_sync(0xffffffffu, sgw,  o);
        sbw  += __shfl_xor_sync(0xffffffffu, sbw,  o);
    }

    if (lane == 0) {
        const float mu  = sx * (1.0f / DD);
        const float var = sx2 * (1.0f / DD) - mu * mu;
        const float rs  = rsqrtf(var + 1e-3f);
        float score = rs * (sxgw - mu * sgw) + sbw + bias[0];
        score += (1.0f - mask[warp]) * -1e9f;
        g_score[warp] = score;
    }
}

// ---------------------------------------------------------------------------
// Kernel 2: softmax over S per batch. One block (1024 thr) per batch,
// 4 elements per thread.
// ---------------------------------------------------------------------------
__global__ __launch_bounds__(1024) void softmax_kernel()
{
    const int b   = blockIdx.x;
    const int tid = threadIdx.x;
    const float* sc = g_score + b * SS;

    __shared__ float red[32];

    float v[4];
    float m = -INFINITY;
    #pragma unroll
    for (int i = 0; i < 4; i++) {
        v[i] = sc[tid + i * 1024];
        m = fmaxf(m, v[i]);
    }
    // block max
    #pragma unroll
    for (int o = 16; o > 0; o >>= 1) m = fmaxf(m, __shfl_xor_sync(~0u, m, o));
    if ((tid & 31) == 0) red[tid >> 5] = m;
    __syncthreads();
    if (tid < 32) {
        float t = red[tid];
        #pragma unroll
        for (int o = 16; o > 0; o >>= 1) t = fmaxf(t, __shfl_xor_sync(~0u, t, o));
        red[tid] = t;
    }
    __syncthreads();
    m = red[0];
    __syncthreads();

    float s = 0.0f;
    #pragma unroll
    for (int i = 0; i < 4; i++) { v[i] = __expf(v[i] - m); s += v[i]; }
    #pragma unroll
    for (int o = 16; o > 0; o >>= 1) s += __shfl_xor_sync(~0u, s, o);
    if ((tid & 31) == 0) red[tid >> 5] = s;
    __syncthreads();
    if (tid < 32) {
        float t = red[tid];
        #pragma unroll
        for (int o = 16; o > 0; o >>= 1) t += __shfl_xor_sync(~0u, t, o);
        red[tid] = t;
    }
    __syncthreads();
    const float inv = 1.0f / red[0];

    float* wt = g_weight + b * SS;
    #pragma unroll
    for (int i = 0; i < 4; i++) wt[tid + i * 1024] = v[i] * inv;
}

// ---------------------------------------------------------------------------
// Kernel 3: weighted sum over S, split across SPLIT blocks per batch.
// Block (kx=split, by=batch), 256 threads: thread t owns column d=t and
// accumulates 128 rows. Weights staged in shared. Fully coalesced row reads.
// ---------------------------------------------------------------------------
__global__ __launch_bounds__(256) void pool_kernel(const float* __restrict__ x)
{
    const int k = blockIdx.x;
    const int b = blockIdx.y;
    const int d = threadIdx.x;

    const int s0 = k * ROWS_PER_SPLIT;
    const float* xb = x + ((size_t)b * SS + s0) * DD;
    const float* wt = g_weight + b * SS + s0;

    __shared__ float sw[ROWS_PER_SPLIT];
    if (d < ROWS_PER_SPLIT) sw[d] = wt[d];
    __syncthreads();

    float acc0 = 0.0f, acc1 = 0.0f, acc2 = 0.0f, acc3 = 0.0f;
    #pragma unroll 4
    for (int s = 0; s < ROWS_PER_SPLIT; s += 4) {
        acc0 += xb[(size_t)(s + 0) * DD + d] * sw[s + 0];
        acc1 += xb[(size_t)(s + 1) * DD + d] * sw[s + 1];
        acc2 += xb[(size_t)(s + 2) * DD + d] * sw[s + 2];
        acc3 += xb[(size_t)(s + 3) * DD + d] * sw[s + 3];
    }
    g_partial[(size_t)k * BB * DD + b * DD + d] = (acc0 + acc1) + (acc2 + acc3);
}

// ---------------------------------------------------------------------------
// Kernel 4: reduce the SPLIT partials -> d_out [B, D]
// ---------------------------------------------------------------------------
__global__ __launch_bounds__(256) void reduce_kernel(float* __restrict__ out)
{
    const int i = blockIdx.x * blockDim.x + threadIdx.x;  // 0 .. B*D-1
    float acc = 0.0f;
    #pragma unroll
    for (int kk = 0; kk < SPLIT; kk++) acc += g_partial[(size_t)kk * BB * DD + i];
    out[i] = acc;
}

// ---------------------------------------------------------------------------
extern "C" void kernel_launch(void* const* d_in, const int* in_sizes, int n_in,
                              void* d_out, int out_size)
{
    const float* x     = (const float*)d_in[0];
    const float* mask  = (const float*)d_in[1];
    const float* gamma = (const float*)d_in[2];
    const float* beta  = (const float*)d_in[3];
    const float* w     = (const float*)d_in[4];
    const float* bias  = (const float*)d_in[5];
    float* out = (float*)d_out;

    // 1 warp per row, 8 warps per block
    const int rows = BB * SS;
    score_kernel<<<rows / 8, 256>>>(x, mask, gamma, beta, w, bias);

    softmax_kernel<<<BB, 1024>>>();

    dim3 g3(SPLIT, BB);
    pool_kernel<<<g3, 256>>>(x);

    reduce_kernel<<<(BB * DD) / 256, 256>>>(out);
}

// round 8
// speedup vs baseline: 2.3071x; 2.3071x over previous
#include <cuda_runtime.h>
#include <math.h>

#define BB 64
#define SS 4096
#define DD 256
#define SPLIT 32
#define ROWS_PER_CHUNK (SS / SPLIT)     // 128 rows per block
#define ROWS_PER_WARP  (ROWS_PER_CHUNK / 8)  // 16 rows per warp
#define NCHUNK (BB * SPLIT)             // 2048

// Scratch partials (no allocation allowed in kernel_launch)
__device__ float g_m[NCHUNK];
__device__ float g_z[NCHUNK];
__device__ float g_acc[NCHUNK * DD];

// ---------------------------------------------------------------------------
// Kernel 1: fused LN-score + online-softmax weighted accumulation.
// Single pass over x. One warp per row, lane owns 8 consecutive d's.
// Per warp maintains (m, Z, acc[8 per lane]); block combines 8 warps in smem.
// ---------------------------------------------------------------------------
__global__ __launch_bounds__(256) void fused_kernel(
    const float* __restrict__ x, const float* __restrict__ mask,
    const float* __restrict__ gamma, const float* __restrict__ beta,
    const float* __restrict__ w, const float* __restrict__ bias)
{
    const int chunk = blockIdx.x;            // 0..2047
    const int b     = chunk / SPLIT;
    const int k     = chunk % SPLIT;
    const int wid   = threadIdx.x >> 5;      // 0..7
    const int lane  = threadIdx.x & 31;
    const int d0    = lane * 8;

    const int s_base = k * ROWS_PER_CHUNK + wid * ROWS_PER_WARP;
    const float* xrow = x + ((size_t)b * SS + s_base) * DD;
    const float* mrow = mask + (size_t)b * SS + s_base;

    // ---- per-lane parameter setup (once) ----
    const float4 g1 = *(const float4*)(gamma + d0);
    const float4 g2 = *(const float4*)(gamma + d0 + 4);
    const float4 w1 = *(const float4*)(w + d0);
    const float4 w2 = *(const float4*)(w + d0 + 4);
    const float4 b1 = *(const float4*)(beta + d0);
    const float4 b2 = *(const float4*)(beta + d0 + 4);

    float gw[8];
    gw[0] = g1.x * w1.x; gw[1] = g1.y * w1.y; gw[2] = g1.z * w1.z; gw[3] = g1.w * w1.w;
    gw[4] = g2.x * w2.x; gw[5] = g2.y * w2.y; gw[6] = g2.z * w2.z; gw[7] = g2.w * w2.w;

    float sgw = gw[0]+gw[1]+gw[2]+gw[3]+gw[4]+gw[5]+gw[6]+gw[7];
    float sbw = b1.x*w1.x + b1.y*w1.y + b1.z*w1.z + b1.w*w1.w
              + b2.x*w2.x + b2.y*w2.y + b2.z*w2.z + b2.w*w2.w;
    #pragma unroll
    for (int o = 16; o > 0; o >>= 1) {
        sgw += __shfl_xor_sync(~0u, sgw, o);
        sbw += __shfl_xor_sync(~0u, sbw, o);
    }
    const float cterm = sbw + bias[0];

    // ---- online softmax accumulation over 16 rows ----
    float acc[8];
    #pragma unroll
    for (int j = 0; j < 8; j++) acc[j] = 0.0f;
    float m = -INFINITY, Z = 0.0f;

    float4 a = *(const float4*)(xrow + d0);
    float4 c = *(const float4*)(xrow + d0 + 4);

    #pragma unroll 4
    for (int r = 0; r < ROWS_PER_WARP; r++) {
        float4 an, cn;
        if (r + 1 < ROWS_PER_WARP) {
            an = *(const float4*)(xrow + (size_t)(r + 1) * DD + d0);
            cn = *(const float4*)(xrow + (size_t)(r + 1) * DD + d0 + 4);
        }

        float sx   = a.x + a.y + a.z + a.w + c.x + c.y + c.z + c.w;
        float sx2  = a.x*a.x + a.y*a.y + a.z*a.z + a.w*a.w
                   + c.x*c.x + c.y*c.y + c.z*c.z + c.w*c.w;
        float sxgw = a.x*gw[0] + a.y*gw[1] + a.z*gw[2] + a.w*gw[3]
                   + c.x*gw[4] + c.y*gw[5] + c.z*gw[6] + c.w*gw[7];
        #pragma unroll
        for (int o = 16; o > 0; o >>= 1) {
            sx   += __shfl_xor_sync(~0u, sx,   o);
            sx2  += __shfl_xor_sync(~0u, sx2,  o);
            sxgw += __shfl_xor_sync(~0u, sxgw, o);
        }
        // butterfly -> every lane has the totals; score identical across warp
        const float mu  = sx * (1.0f / DD);
        const float var = sx2 * (1.0f / DD) - mu * mu;
        const float rs  = rsqrtf(var + 1e-3f);
        float score = rs * (sxgw - mu * sgw) + cterm;
        score += (1.0f - mrow[r]) * -1e9f;

        const float newm   = fmaxf(m, score);
        const float sc_old = __expf(m - newm);      // m=-inf first iter -> 0
        const float p      = __expf(score - newm);
        Z = Z * sc_old + p;
        acc[0] = acc[0] * sc_old + p * a.x;
        acc[1] = acc[1] * sc_old + p * a.y;
        acc[2] = acc[2] * sc_old + p * a.z;
        acc[3] = acc[3] * sc_old + p * a.w;
        acc[4] = acc[4] * sc_old + p * c.x;
        acc[5] = acc[5] * sc_old + p * c.y;
        acc[6] = acc[6] * sc_old + p * c.z;
        acc[7] = acc[7] * sc_old + p * c.w;
        m = newm;

        a = an; c = cn;
    }

    // ---- block-level combine of the 8 warp partials ----
    __shared__ float s_m[8];
    __shared__ float s_z[8];
    __shared__ float s_acc[8][DD];

    if (lane == 0) { s_m[wid] = m; s_z[wid] = Z; }
    __syncthreads();

    float M = s_m[0];
    #pragma unroll
    for (int t = 1; t < 8; t++) M = fmaxf(M, s_m[t]);

    const float myscale = __expf(m - M);
    #pragma unroll
    for (int j = 0; j < 8; j++) s_acc[wid][d0 + j] = acc[j] * myscale;
    __syncthreads();

    // thread t sums column t over the 8 warps (fixed order -> deterministic)
    const int t = threadIdx.x;
    float asum = 0.0f;
    #pragma unroll
    for (int ww = 0; ww < 8; ww++) asum += s_acc[ww][t];
    g_acc[(size_t)chunk * DD + t] = asum;

    if (t == 0) {
        float Zb = 0.0f;
        #pragma unroll
        for (int ww = 0; ww < 8; ww++) Zb += s_z[ww] * __expf(s_m[ww] - M);
        g_m[chunk] = M;
        g_z[chunk] = Zb;
    }
}

// ---------------------------------------------------------------------------
// Kernel 2: deterministic 32-way combine per batch -> out [B, D]
// ---------------------------------------------------------------------------
__global__ __launch_bounds__(256) void combine_kernel(float* __restrict__ out)
{
    const int b = blockIdx.x;
    const int d = threadIdx.x;

    __shared__ float s_m[SPLIT];
    __shared__ float s_scale[SPLIT];

    if (d < SPLIT) s_m[d] = g_m[b * SPLIT + d];
    __syncthreads();

    float M = s_m[0];
    #pragma unroll
    for (int kk = 1; kk < SPLIT; kk++) M = fmaxf(M, s_m[kk]);

    if (d < SPLIT) s_scale[d] = __expf(s_m[d] - M);
    __syncthreads();

    float asum = 0.0f, zsum = 0.0f;
    #pragma unroll
    for (int kk = 0; kk < SPLIT; kk++) {
        const float sc = s_scale[kk];
        asum += g_acc[(size_t)(b * SPLIT + kk) * DD + d] * sc;
        zsum += g_z[b * SPLIT + kk] * sc;
    }
    out[b * DD + d] = asum / zsum;
}

// ---------------------------------------------------------------------------
extern "C" void kernel_launch(void* const* d_in, const int* in_sizes, int n_in,
                              void* d_out, int out_size)
{
    const float* x     = (const float*)d_in[0];
    const float* mask  = (const float*)d_in[1];
    const float* gamma = (const float*)d_in[2];
    const float* beta  = (const float*)d_in[3];
    const float* w     = (const float*)d_in[4];
    const float* bias  = (const float*)d_in[5];
    float* out = (float*)d_out;

    fused_kernel<<<NCHUNK, 256>>>(x, mask, gamma, beta, w, bias);
    combine_kernel<<<BB, 256>>>(out);
}

// round 10
// speedup vs baseline: 2.4279x; 1.0524x over previous
#include <cuda_runtime.h>
#include <math.h>

#define BB 64
#define SS 4096
#define DD 256
#define SPLIT 32
#define ROWS_PER_CHUNK (SS / SPLIT)          // 128 rows per block
#define ROWS_PER_WARP  (ROWS_PER_CHUNK / 8)  // 16 rows per warp
#define NCHUNK (BB * SPLIT)                  // 2048

// Scratch partials (no allocation allowed in kernel_launch)
__device__ float g_m[NCHUNK];
__device__ float g_z[NCHUNK];
__device__ float g_acc[NCHUNK * DD];

// ---------------------------------------------------------------------------
// Kernel 1: fused LN-score + online-softmax weighted accumulation.
// Single pass over x. One warp per row, lane owns 8 consecutive d's.
// Online update uses a single __expf per row (one of the two scales is 1).
// ---------------------------------------------------------------------------
__global__ __launch_bounds__(256) void fused_kernel(
    const float* __restrict__ x, const float* __restrict__ mask,
    const float* __restrict__ gamma, const float* __restrict__ beta,
    const float* __restrict__ w, const float* __restrict__ bias)
{
    const int chunk = blockIdx.x;            // 0..2047
    const int b     = chunk / SPLIT;
    const int k     = chunk % SPLIT;
    const int wid   = threadIdx.x >> 5;      // 0..7
    const int lane  = threadIdx.x & 31;
    const int d0    = lane * 8;

    const int s_base = k * ROWS_PER_CHUNK + wid * ROWS_PER_WARP;
    const float* xrow = x + ((size_t)b * SS + s_base) * DD;
    const float* mrow = mask + (size_t)b * SS + s_base;

    // ---- per-lane parameter setup (once) ----
    const float4 g1 = *(const float4*)(gamma + d0);
    const float4 g2 = *(const float4*)(gamma + d0 + 4);
    const float4 w1 = *(const float4*)(w + d0);
    const float4 w2 = *(const float4*)(w + d0 + 4);
    const float4 b1 = *(const float4*)(beta + d0);
    const float4 b2 = *(const float4*)(beta + d0 + 4);

    float gw[8];
    gw[0] = g1.x * w1.x; gw[1] = g1.y * w1.y; gw[2] = g1.z * w1.z; gw[3] = g1.w * w1.w;
    gw[4] = g2.x * w2.x; gw[5] = g2.y * w2.y; gw[6] = g2.z * w2.z; gw[7] = g2.w * w2.w;

    float sgw = gw[0]+gw[1]+gw[2]+gw[3]+gw[4]+gw[5]+gw[6]+gw[7];
    float sbw = b1.x*w1.x + b1.y*w1.y + b1.z*w1.z + b1.w*w1.w
              + b2.x*w2.x + b2.y*w2.y + b2.z*w2.z + b2.w*w2.w;
    #pragma unroll
    for (int o = 16; o > 0; o >>= 1) {
        sgw += __shfl_xor_sync(~0u, sgw, o);
        sbw += __shfl_xor_sync(~0u, sbw, o);
    }
    const float cterm = sbw + bias[0];

    // Preload this warp's 16 mask values into lanes 0..15 (off the hot path)
    const float mval = (lane < ROWS_PER_WARP) ? mrow[lane] : 0.0f;

    // ---- online softmax accumulation over 16 rows ----
    float acc[8];
    #pragma unroll
    for (int j = 0; j < 8; j++) acc[j] = 0.0f;
    float m = -INFINITY, Z = 0.0f;

    float4 a = *(const float4*)(xrow + d0);
    float4 c = *(const float4*)(xrow + d0 + 4);

    #pragma unroll 4
    for (int r = 0; r < ROWS_PER_WARP; r++) {
        float4 an, cn;
        if (r + 1 < ROWS_PER_WARP) {
            an = *(const float4*)(xrow + (size_t)(r + 1) * DD + d0);
            cn = *(const float4*)(xrow + (size_t)(r + 1) * DD + d0 + 4);
        }

        float sx   = a.x + a.y + a.z + a.w + c.x + c.y + c.z + c.w;
        float sx2  = a.x*a.x + a.y*a.y + a.z*a.z + a.w*a.w
                   + c.x*c.x + c.y*c.y + c.z*c.z + c.w*c.w;
        float sxgw = a.x*gw[0] + a.y*gw[1] + a.z*gw[2] + a.w*gw[3]
                   + c.x*gw[4] + c.y*gw[5] + c.z*gw[6] + c.w*gw[7];
        #pragma unroll
        for (int o = 16; o > 0; o >>= 1) {
            sx   += __shfl_xor_sync(~0u, sx,   o);
            sx2  += __shfl_xor_sync(~0u, sx2,  o);
            sxgw += __shfl_xor_sync(~0u, sxgw, o);
        }
        const float mk  = __shfl_sync(~0u, mval, r);
        const float mu  = sx * (1.0f / DD);
        const float var = sx2 * (1.0f / DD) - mu * mu;
        const float rs  = rsqrtf(var + 1e-3f);
        float score = rs * (sxgw - mu * sgw) + cterm;
        score += (1.0f - mk) * -1e9f;

        // single-exp online update: one of {sc, p} is exactly 1
        const float dlt = score - m;                 // +inf on first iter
        const bool  up  = dlt > 0.0f;
        const float e   = __expf(up ? -dlt : dlt);   // exp(-|dlt|); 0 on first iter
        const float sc  = up ? e : 1.0f;
        const float p   = up ? 1.0f : e;
        if (up) m = score;

        Z = Z * sc + p;
        acc[0] = acc[0] * sc + p * a.x;
        acc[1] = acc[1] * sc + p * a.y;
        acc[2] = acc[2] * sc + p * a.z;
        acc[3] = acc[3] * sc + p * a.w;
        acc[4] = acc[4] * sc + p * c.x;
        acc[5] = acc[5] * sc + p * c.y;
        acc[6] = acc[6] * sc + p * c.z;
        acc[7] = acc[7] * sc + p * c.w;

        a = an; c = cn;
    }

    // ---- block-level combine of the 8 warp partials ----
    __shared__ float s_m[8];
    __shared__ float s_z[8];
    __shared__ float s_acc[8][DD];

    if (lane == 0) { s_m[wid] = m; s_z[wid] = Z; }
    __syncthreads();

    float M = s_m[0];
    #pragma unroll
    for (int t = 1; t < 8; t++) M = fmaxf(M, s_m[t]);

    const float myscale = __expf(m - M);
    #pragma unroll
    for (int j = 0; j < 8; j++) s_acc[wid][d0 + j] = acc[j] * myscale;
    __syncthreads();

    const int t = threadIdx.x;
    float asum = 0.0f;
    #pragma unroll
    for (int ww = 0; ww < 8; ww++) asum += s_acc[ww][t];
    g_acc[(size_t)chunk * DD + t] = asum;

    if (t == 0) {
        float Zb = 0.0f;
        #pragma unroll
        for (int ww = 0; ww < 8; ww++) Zb += s_z[ww] * __expf(s_m[ww] - M);
        g_m[chunk] = M;
        g_z[chunk] = Zb;
    }
}

// ---------------------------------------------------------------------------
// Kernel 2: deterministic 32-way combine per batch -> out [B, D].
// 1024 threads: 4 groups x 256 columns; each group sums 8 chunks, then a
// fixed-order 4-way group sum (same overall kk order 0..31 as before).
// ---------------------------------------------------------------------------
__global__ __launch_bounds__(1024) void combine_kernel(float* __restrict__ out)
{
    const int b = blockIdx.x;
    const int g = threadIdx.x >> 8;    // 0..3
    const int d = threadIdx.x & 255;   // 0..255

    __shared__ float s_m[SPLIT];
    __shared__ float s_z[SPLIT];
    __shared__ float s_sc[SPLIT];
    __shared__ float s_part[4][DD];

    if (threadIdx.x < SPLIT) {
        s_m[threadIdx.x] = g_m[b * SPLIT + threadIdx.x];
        s_z[threadIdx.x] = g_z[b * SPLIT + threadIdx.x];
    }
    __syncthreads();

    float M = s_m[0];
    #pragma unroll
    for (int kk = 1; kk < SPLIT; kk++) M = fmaxf(M, s_m[kk]);

    if (threadIdx.x < SPLIT) s_sc[threadIdx.x] = __expf(s_m[threadIdx.x] - M);
    __syncthreads();

    // group g sums chunks kk = 8g .. 8g+7 for its column d (coalesced, MLP=8)
    float asum = 0.0f;
    #pragma unroll
    for (int j = 0; j < 8; j++) {
        const int kk = g * 8 + j;
        asum += g_acc[(size_t)(b * SPLIT + kk) * DD + d] * s_sc[kk];
    }
    s_part[g][d] = asum;
    __syncthreads();

    if (g == 0) {
        // Z total: fixed order kk=0..31, computed redundantly per thread
        float zsum = 0.0f;
        #pragma unroll
        for (int kk = 0; kk < SPLIT; kk++) zsum += s_z[kk] * s_sc[kk];

        const float total = ((s_part[0][d] + s_part[1][d])
                           + (s_part[2][d] + s_part[3][d]));
        out[b * DD + d] = total / zsum;
    }
}

// ---------------------------------------------------------------------------
extern "C" void kernel_launch(void* const* d_in, const int* in_sizes, int n_in,
                              void* d_out, int out_size)
{
    const float* x     = (const float*)d_in[0];
    const float* mask  = (const float*)d_in[1];
    const float* gamma = (const float*)d_in[2];
    const float* beta  = (const float*)d_in[3];
    const float* w     = (const float*)d_in[4];
    const float* bias  = (const float*)d_in[5];
    float* out = (float*)d_out;

    fused_kernel<<<NCHUNK, 256>>>(x, mask, gamma, beta, w, bias);
    combine_kernel<<<BB, 1024>>>(out);
}